// round 1
// baseline (speedup 1.0000x reference)
#include <cuda_runtime.h>
#include <math.h>

#define Bn 256
#define Mn 512
#define Dn 512
#define Cn 8
#define U1 512
#define U2 256
#define U3 128

// Scratch (no allocation allowed -> __device__ globals)
__device__ float g_pooled[Bn * Dn];          // (B, D)
__device__ float g_h1[Cn * Bn * U1];         // (C, B, 512)
__device__ float g_h2[Cn * Bn * U2];         // (C, B, 256)
__device__ float g_h3[Cn * Bn * U3];         // (C, B, 128)
__device__ float g_term[Cn * Bn];            // per (c,b) loss term

// ---------------------------------------------------------------------------
// 1) Masked sum pooling: pooled[b,d] = sum_m ec[b,m,d] * (mask[b,m]==0)
//    grid (B, 2), 256 threads; each block handles one b and half of D.
// ---------------------------------------------------------------------------
__global__ void pool_kernel(const float* __restrict__ ec,
                            const float* __restrict__ mask) {
    const int b = blockIdx.x;
    const int dbase = blockIdx.y * 256;
    const int tid = threadIdx.x;

    __shared__ float keep[Mn];
    for (int i = tid; i < Mn; i += 256)
        keep[i] = (mask[b * Mn + i] == 0.0f) ? 1.0f : 0.0f;
    __syncthreads();

    const float* p = ec + ((size_t)b * Mn) * Dn + dbase + tid;
    float acc = 0.0f;
#pragma unroll 4
    for (int m = 0; m < Mn; m++)
        acc = fmaf(p[(size_t)m * Dn], keep[m], acc);

    g_pooled[b * Dn + dbase + tid] = acc;
}

// ---------------------------------------------------------------------------
// 2) Tiled GEMM + bias + relu, one template per layer.
//    out[c,b,n] = relu( sum_k A[(c?),b,k] * W[c,k,n] + bias[c,n] )
//    64x64 tile, K-step 32, 256 threads, 4x4 micro-tile per thread.
// ---------------------------------------------------------------------------
template <int LAYER>
__global__ void gemm_relu_kernel(const float* __restrict__ W,
                                 const float* __restrict__ bias) {
    constexpr int K = (LAYER == 1) ? Dn : (LAYER == 2) ? U1 : U2;
    constexpr int N = (LAYER == 1) ? U1 : (LAYER == 2) ? U2 : U3;
    constexpr bool AHASC = (LAYER != 1);

    const float* Aroot = (LAYER == 1) ? g_pooled : (LAYER == 2) ? g_h1 : g_h2;
    float* Oroot       = (LAYER == 1) ? g_h1     : (LAYER == 2) ? g_h2 : g_h3;

    const int c  = blockIdx.z;
    const int b0 = blockIdx.y * 64;
    const int n0 = blockIdx.x * 64;
    const int tid = threadIdx.x;
    const int tb = tid >> 4;       // 0..15
    const int tn = tid & 15;       // 0..15

    __shared__ float As[32][68];   // [k][b]   (padded, 16B-aligned rows)
    __shared__ float Ws[32][68];   // [k][n]

    float acc[4][4] = {};

    const float* Ag = Aroot + (AHASC ? (size_t)c * Bn * K : 0) + (size_t)b0 * K;
    const float* Wg = W + (size_t)c * K * N + n0;

    const int arow = tid >> 2;          // 0..63 (b within tile)
    const int acol = (tid & 3) * 8;     // 0..24 (k within tile)
    const int wrow = tid >> 3;          // 0..31 (k within tile)
    const int wcol = (tid & 7) * 8;     // 0..56 (n within tile)

    for (int k0 = 0; k0 < K; k0 += 32) {
        float4 a0 = *(const float4*)(Ag + (size_t)arow * K + k0 + acol);
        float4 a1 = *(const float4*)(Ag + (size_t)arow * K + k0 + acol + 4);
        float4 w0 = *(const float4*)(Wg + (size_t)(k0 + wrow) * N + wcol);
        float4 w1 = *(const float4*)(Wg + (size_t)(k0 + wrow) * N + wcol + 4);

        __syncthreads();  // previous tile fully consumed
        As[acol + 0][arow] = a0.x; As[acol + 1][arow] = a0.y;
        As[acol + 2][arow] = a0.z; As[acol + 3][arow] = a0.w;
        As[acol + 4][arow] = a1.x; As[acol + 5][arow] = a1.y;
        As[acol + 6][arow] = a1.z; As[acol + 7][arow] = a1.w;
        *(float4*)&Ws[wrow][wcol]     = w0;
        *(float4*)&Ws[wrow][wcol + 4] = w1;
        __syncthreads();

#pragma unroll
        for (int k = 0; k < 32; k++) {
            float4 av = *(const float4*)&As[k][tb * 4];
            float4 wv = *(const float4*)&Ws[k][tn * 4];
            float a[4] = {av.x, av.y, av.z, av.w};
            float w[4] = {wv.x, wv.y, wv.z, wv.w};
#pragma unroll
            for (int i = 0; i < 4; i++)
#pragma unroll
                for (int j = 0; j < 4; j++)
                    acc[i][j] = fmaf(a[i], w[j], acc[i][j]);
        }
    }

    const float* bptr = bias + c * N + n0 + tn * 4;
    float bx = bptr[0], by = bptr[1], bz = bptr[2], bw = bptr[3];
#pragma unroll
    for (int i = 0; i < 4; i++) {
        const int b = b0 + tb * 4 + i;
        float4 o;
        o.x = fmaxf(acc[i][0] + bx, 0.0f);
        o.y = fmaxf(acc[i][1] + by, 0.0f);
        o.z = fmaxf(acc[i][2] + bz, 0.0f);
        o.w = fmaxf(acc[i][3] + bw, 0.0f);
        *(float4*)(Oroot + ((size_t)(c * Bn + b)) * N + n0 + tn * 4) = o;
    }
}

// ---------------------------------------------------------------------------
// 3) L2 normalize rows of h3 -> z (written straight into d_out).
//    One warp per (c,b) row of 128 floats.
// ---------------------------------------------------------------------------
__global__ void norm_kernel(float* __restrict__ zout) {
    const int warp = threadIdx.x >> 5;
    const int lane = threadIdx.x & 31;
    const int cb = blockIdx.x * 8 + warp;   // 0..2047

    const float4 v = *(const float4*)(g_h3 + (size_t)cb * U3 + lane * 4);
    float ss = v.x * v.x + v.y * v.y + v.z * v.z + v.w * v.w;
#pragma unroll
    for (int o = 16; o; o >>= 1) ss += __shfl_xor_sync(0xffffffffu, ss, o);
    const float r = rsqrtf(fmaxf(ss, 1e-12f));
    float4 ov = {v.x * r, v.y * r, v.z * r, v.w * r};
    *(float4*)(zout + (size_t)cb * U3 + lane * 4) = ov;
}

// ---------------------------------------------------------------------------
// 4) Per-(c,b) contrastive term.
//    grid (C, 32); block = 8 warps, warp handles one b.
//    z[c] (256x128) staged in shared with 132-float padded rows.
// ---------------------------------------------------------------------------
#define ZPAD 132
__global__ void loss_kernel(const float* __restrict__ z,
                            const int* __restrict__ label) {
    extern __shared__ float zs[];          // [256][ZPAD]
    __shared__ int slab[Bn];
    __shared__ int s_nump;

    const int c = blockIdx.x;
    const int tid = threadIdx.x;           // 256
    const int lane = tid & 31;
    const int warp = tid >> 5;

    // stage z[c] -> shared (coalesced float4)
    const float* zc = z + (size_t)c * Bn * U3;
    for (int idx = tid; idx < Bn * U3 / 4; idx += 256) {
        const int row = idx >> 5;          // /32 float4 per row
        const int c4 = idx & 31;
        float4 v = *(const float4*)(zc + (size_t)row * U3 + c4 * 4);
        *(float4*)&zs[row * ZPAD + c4 * 4] = v;
    }
    slab[tid] = label[tid * Cn + c];
    __syncthreads();
    if (tid == 0) {
        int s = 0;
        for (int i = 0; i < Bn; i++) s += slab[i];
        s_nump = s;
    }
    __syncthreads();

    const int b = blockIdx.y * 8 + warp;
    const int labb = slab[b];
    const int nump = s_nump;
    const int numv = labb ? nump : (Bn - nump);
    const float* zb = &zs[b * ZPAD];

    float expsum = 0.0f, psum = 0.0f;
#pragma unroll
    for (int kk = 0; kk < 8; kk++) {
        const int k = kk * 32 + lane;
        const float* zk = &zs[k * ZPAD];
        float s = 0.0f;
#pragma unroll
        for (int j = 0; j < U3; j += 4) {
            float4 a = *(const float4*)(zb + j);  // broadcast
            float4 x = *(const float4*)(zk + j);
            s = fmaf(a.x, x.x, s);
            s = fmaf(a.y, x.y, s);
            s = fmaf(a.z, x.z, s);
            s = fmaf(a.w, x.w, s);
        }
        const float ipv = (k == b) ? 0.0f : s * 2.0f;   // /TEMP, diag zeroed
        expsum += expf(ipv);
        psum += (slab[k] == labb) ? ipv : 0.0f;
    }
#pragma unroll
    for (int o = 16; o; o >>= 1) {
        expsum += __shfl_xor_sync(0xffffffffu, expsum, o);
        psum   += __shfl_xor_sync(0xffffffffu, psum, o);
    }
    if (lane == 0)
        g_term[c * Bn + b] = psum / (float)numv - logf(expsum);
}

// ---------------------------------------------------------------------------
// 5) Reduce terms -> losses[c] (deterministic tree reduce)
// ---------------------------------------------------------------------------
__global__ void final_kernel(float* __restrict__ out) {
    __shared__ float red[Bn];
    const int c = blockIdx.x;
    const int tid = threadIdx.x;
    red[tid] = g_term[c * Bn + tid];
    __syncthreads();
    for (int s = 128; s; s >>= 1) {
        if (tid < s) red[tid] += red[tid + s];
        __syncthreads();
    }
    if (tid == 0) out[(size_t)Cn * Bn * U3 + c] = -red[0];
}

// ---------------------------------------------------------------------------
extern "C" void kernel_launch(void* const* d_in, const int* in_sizes, int n_in,
                              void* d_out, int out_size) {
    const float* ec    = (const float*)d_in[0];
    const float* mask  = (const float*)d_in[1];
    const int*   label = (const int*)d_in[2];
    const float* W1    = (const float*)d_in[3];
    const float* b1    = (const float*)d_in[4];
    const float* W2    = (const float*)d_in[5];
    const float* b2    = (const float*)d_in[6];
    const float* W3    = (const float*)d_in[7];
    const float* b3    = (const float*)d_in[8];
    float* out = (float*)d_out;

    const int loss_smem = Bn * ZPAD * (int)sizeof(float);
    cudaFuncSetAttribute(loss_kernel,
                         cudaFuncAttributeMaxDynamicSharedMemorySize, loss_smem);

    pool_kernel<<<dim3(Bn, 2), 256>>>(ec, mask);
    gemm_relu_kernel<1><<<dim3(U1 / 64, Bn / 64, Cn), 256>>>(W1, b1);
    gemm_relu_kernel<2><<<dim3(U2 / 64, Bn / 64, Cn), 256>>>(W2, b2);
    gemm_relu_kernel<3><<<dim3(U3 / 64, Bn / 64, Cn), 256>>>(W3, b3);
    norm_kernel<<<Cn * Bn / 8, 256>>>(out);
    loss_kernel<<<dim3(Cn, Bn / 8), 256, loss_smem>>>(out, label);
    final_kernel<<<Cn, Bn>>>(out);
}